// round 10
// baseline (speedup 1.0000x reference)
#include <cuda_runtime.h>

#define M_SLOTS 16
#define KEY_DIM 1024
#define TPB     256

// Cross-block handshake. Zero-initialized at load; last block of every
// launch resets it so each graph replay starts clean (deterministic).
__device__ float        g_wbuf[M_SLOTS];
__device__ unsigned int g_flag;   // 0 = not ready, 1 = weights published
__device__ unsigned int g_done;   // completion counter for reset

// ---------------------------------------------------------------------------
// Phase A (block 0 only), out-of-line so its register pressure cannot
// inflate the streaming path's allocation.
// ---------------------------------------------------------------------------
__device__ __noinline__ void compute_weights(const float* __restrict__ task_emb,
                                             const float* __restrict__ K_memory,
                                             float* s_w) {
    __shared__ float s_cos[M_SLOTS];
    const int tid  = threadIdx.x;
    const int warp = tid >> 5;
    const int lane = tid & 31;
    const int sa = 2 * warp, sb = 2 * warp + 1;

    const float4* t4 = (const float4*)task_emb;
    const float4* ka = (const float4*)(K_memory + sa * KEY_DIM);
    const float4* kb = (const float4*)(K_memory + sb * KEY_DIM);

    float dota = 0.f, dotb = 0.f, kka = 0.f, kkb = 0.f, tt = 0.f;
    #pragma unroll
    for (int j = 0; j < 8; j++) {
        float4 t = t4[lane + 32 * j];
        float4 a = ka[lane + 32 * j];
        float4 b = kb[lane + 32 * j];
        dota = fmaf(t.x, a.x, dota); dota = fmaf(t.y, a.y, dota);
        dota = fmaf(t.z, a.z, dota); dota = fmaf(t.w, a.w, dota);
        dotb = fmaf(t.x, b.x, dotb); dotb = fmaf(t.y, b.y, dotb);
        dotb = fmaf(t.z, b.z, dotb); dotb = fmaf(t.w, b.w, dotb);
        kka  = fmaf(a.x, a.x, kka);  kka  = fmaf(a.y, a.y, kka);
        kka  = fmaf(a.z, a.z, kka);  kka  = fmaf(a.w, a.w, kka);
        kkb  = fmaf(b.x, b.x, kkb);  kkb  = fmaf(b.y, b.y, kkb);
        kkb  = fmaf(b.z, b.z, kkb);  kkb  = fmaf(b.w, b.w, kkb);
        tt   = fmaf(t.x, t.x, tt);   tt   = fmaf(t.y, t.y, tt);
        tt   = fmaf(t.z, t.z, tt);   tt   = fmaf(t.w, t.w, tt);
    }
    #pragma unroll
    for (int off = 16; off > 0; off >>= 1) {
        dota += __shfl_down_sync(0xffffffffu, dota, off);
        dotb += __shfl_down_sync(0xffffffffu, dotb, off);
        kka  += __shfl_down_sync(0xffffffffu, kka,  off);
        kkb  += __shfl_down_sync(0xffffffffu, kkb,  off);
        tt   += __shfl_down_sync(0xffffffffu, tt,   off);
    }
    if (lane == 0) {
        float n1 = sqrtf(tt);
        s_cos[sa] = dota / fmaxf(n1 * sqrtf(kka), 1e-6f);
        s_cos[sb] = dotb / fmaxf(n1 * sqrtf(kkb), 1e-6f);
    }
    __syncthreads();

    if (tid == 0) {
        float c[M_SLOTS];
        float mx = -1e30f;
        #pragma unroll
        for (int m = 0; m < M_SLOTS; m++) { c[m] = s_cos[m]; mx = fmaxf(mx, c[m]); }
        float sum = 0.f;
        #pragma unroll
        for (int m = 0; m < M_SLOTS; m++) { c[m] = __expf(c[m] - mx); sum += c[m]; }
        float inv = 1.0f / sum;
        #pragma unroll
        for (int m = 0; m < M_SLOTS; m++) {
            float wm = c[m] * inv;
            s_w[m]    = wm;
            g_wbuf[m] = wm;
        }
        __threadfence();
        unsigned int* fp = &g_flag;
        asm volatile("st.release.gpu.u32 [%0], %1;" :: "l"(fp), "r"(1u) : "memory");
    }
    __syncthreads();
}

// ---------------------------------------------------------------------------
// Single fused kernel; streaming body identical to the proven 53.8us loop.
// ONLY change vs R9: exponential-backoff spin (the fixed 128ns poll from
// 1184 concurrent blocks saturated the single LTS slice holding g_flag).
// ---------------------------------------------------------------------------
__global__ void __launch_bounds__(TPB, 8) fused_kernel(
        const float*  __restrict__ task_emb,
        const float*  __restrict__ K_memory,
        const float4* __restrict__ V0,
        const float4* __restrict__ V1,
        float4*       __restrict__ out,
        int nv4_0, int nv4_1) {
    __shared__ float s_w[M_SLOTS];
    const int tid = threadIdx.x;

    if (blockIdx.x == 0) {
        compute_weights(task_emb, K_memory, s_w);
    } else {
        if (tid == 0) {
            unsigned int* fp = &g_flag;
            unsigned int f;
            unsigned int ns = 256;
            while (true) {
                asm volatile("ld.acquire.gpu.u32 %0, [%1];" : "=r"(f) : "l"(fp) : "memory");
                if (f) break;
                __nanosleep(ns);
                if (ns < 8192) ns <<= 1;   // 256,512,...,8192: ~5-8 polls total
            }
        }
        __syncthreads();                    // tid0's acquire orders the reads below
        if (tid < M_SLOTS) s_w[tid] = g_wbuf[tid];
        __syncthreads();
    }

    // ---------------- streaming weighted sum (proven body) ----------------
    const int i = blockIdx.x * TPB + tid;   // grid is an exact fit
    const float4* __restrict__ V;
    size_t stride;
    int idx;
    if (i < nv4_0) { V = V0; idx = i;          stride = (size_t)nv4_0; }
    else           { V = V1; idx = i - nv4_0;  stride = (size_t)nv4_1; }

    float4 acc = make_float4(0.f, 0.f, 0.f, 0.f);
    #pragma unroll
    for (int m = 0; m < M_SLOTS; m++) {
        float4 v = V[(size_t)m * stride + (size_t)idx];
        float wm = s_w[m];
        acc.x = fmaf(wm, v.x, acc.x);
        acc.y = fmaf(wm, v.y, acc.y);
        acc.z = fmaf(wm, v.z, acc.z);
        acc.w = fmaf(wm, v.w, acc.w);
    }
    out[i] = acc;

    // ---------------- reset handshake for the next graph replay ------------
    if (tid == 0) {
        __threadfence();
        unsigned int d = atomicAdd(&g_done, 1u);
        if (d == gridDim.x - 1) {           // last block: all spins have passed
            g_done = 0;
            g_flag = 0;
        }
    }
}

// ---------------------------------------------------------------------------
// Launch contract
// Inputs (metadata order): task_emb [1,1024] f32, K_memory [16,1024] f32,
//                          V0 [16,1024,1024] f32, V1 [16,1024,4096] f32
// Output: rec0 [1024,1024] f32 followed by rec1 [1024,4096] f32
// ---------------------------------------------------------------------------
extern "C" void kernel_launch(void* const* d_in, const int* in_sizes, int n_in,
                              void* d_out, int out_size) {
    const float* task_emb = (const float*)d_in[0];
    const float* K_memory = (const float*)d_in[1];
    const float* V0       = (const float*)d_in[2];
    const float* V1       = (const float*)d_in[3];
    float* out = (float*)d_out;

    const int n0 = in_sizes[2] / M_SLOTS;   // 1024*1024
    const int n1 = in_sizes[3] / M_SLOTS;   // 1024*4096
    const int nv4_0 = n0 / 4;               // 262144
    const int nv4_1 = n1 / 4;               // 1048576
    const int total = nv4_0 + nv4_1;        // 1310720 = 5120 * 256 exactly

    fused_kernel<<<total / TPB, TPB>>>(task_emb, K_memory,
                                       (const float4*)V0, (const float4*)V1,
                                       (float4*)out, nv4_0, nv4_1);
}

// round 11
// speedup vs baseline: 1.0726x; 1.0726x over previous
#include <cuda_runtime.h>

#define M_SLOTS 16
#define KEY_DIM 1024
#define TPB     256

// Weights pipeline state. Zero-initialized at load; the last block of each
// weights launch resets g_cnt, so every graph replay starts clean.
__device__ float        g_w[M_SLOTS];      // final softmax weights
__device__ float        g_dot[M_SLOTS];    // per-slot dot(task, key)
__device__ float        g_kk[M_SLOTS];     // per-slot ||key||^2
__device__ unsigned int g_cnt;             // arrival counter

// ---------------------------------------------------------------------------
// Kernel 1: weights, parallelized across 16 blocks (one per memory slot).
// Each thread loads exactly one float4 of key and task (256 f4 = KEY_DIM).
// Last-arriving block performs the softmax. Critical path ~ one DRAM trip.
// ---------------------------------------------------------------------------
__global__ void __launch_bounds__(TPB) weights_kernel(
        const float* __restrict__ task_emb,
        const float* __restrict__ K_memory) {
#if __CUDA_ARCH__ >= 900
    cudaTriggerProgrammaticLaunchCompletion();
#endif
    __shared__ float s_dot[8], s_kk[8], s_tt[8];
    __shared__ unsigned int s_last;

    const int m    = blockIdx.x;          // slot
    const int tid  = threadIdx.x;
    const int warp = tid >> 5;
    const int lane = tid & 31;

    float4 t = ((const float4*)task_emb)[tid];
    float4 k = ((const float4*)(K_memory + m * KEY_DIM))[tid];

    float dot = t.x * k.x + t.y * k.y + t.z * k.z + t.w * k.w;
    float kk  = k.x * k.x + k.y * k.y + k.z * k.z + k.w * k.w;
    float tt  = t.x * t.x + t.y * t.y + t.z * t.z + t.w * t.w;

    #pragma unroll
    for (int off = 16; off > 0; off >>= 1) {
        dot += __shfl_down_sync(0xffffffffu, dot, off);
        kk  += __shfl_down_sync(0xffffffffu, kk,  off);
        tt  += __shfl_down_sync(0xffffffffu, tt,  off);
    }
    if (lane == 0) { s_dot[warp] = dot; s_kk[warp] = kk; s_tt[warp] = tt; }
    __syncthreads();

    if (tid == 0) {
        float d = 0.f, q = 0.f, r = 0.f;
        #pragma unroll
        for (int w = 0; w < 8; w++) { d += s_dot[w]; q += s_kk[w]; r += s_tt[w]; }
        g_dot[m] = d;
        g_kk[m]  = q;
        __threadfence();                       // publish partials
        s_last = atomicAdd(&g_cnt, 1u);        // arrival order
        // keep r (=||task||^2) for possible final use
        s_tt[0] = r;
    }
    __syncthreads();

    // Last-arriving block finalizes: cos -> softmax -> g_w, reset counter.
    if (tid == 0 && s_last == (unsigned)(M_SLOTS - 1)) {
        __threadfence();                       // acquire all partials
        float n1 = sqrtf(s_tt[0]);             // this block's own ||task||
        float c[M_SLOTS];
        float mx = -1e30f;
        #pragma unroll
        for (int j = 0; j < M_SLOTS; j++) {
            c[j] = g_dot[j] / fmaxf(n1 * sqrtf(g_kk[j]), 1e-6f);
            mx = fmaxf(mx, c[j]);
        }
        float sum = 0.f;
        #pragma unroll
        for (int j = 0; j < M_SLOTS; j++) { c[j] = __expf(c[j] - mx); sum += c[j]; }
        float inv = 1.0f / sum;
        #pragma unroll
        for (int j = 0; j < M_SLOTS; j++) g_w[j] = c[j] * inv;
        g_cnt = 0;                             // reset for next graph replay
    }
}

// ---------------------------------------------------------------------------
// Kernel 2: streaming weighted sum (proven 53.8us / 82.8%-DRAM body).
// ---------------------------------------------------------------------------
__global__ void __launch_bounds__(TPB) wsum_fused_kernel(
        const float4* __restrict__ V0,
        const float4* __restrict__ V1,
        float4* __restrict__ out,
        int nv4_0, int nv4_1) {
    const int i = blockIdx.x * TPB + threadIdx.x;   // grid is an exact fit

    const float4* __restrict__ V;
    size_t stride;
    int idx;
    if (i < nv4_0) { V = V0; idx = i;          stride = (size_t)nv4_0; }
    else           { V = V1; idx = i - nv4_0;  stride = (size_t)nv4_1; }

#if __CUDA_ARCH__ >= 900
    cudaGridDependencySynchronize();
#endif

    float4 acc = make_float4(0.f, 0.f, 0.f, 0.f);
    #pragma unroll
    for (int m = 0; m < M_SLOTS; m++) {
        float4 v = V[(size_t)m * stride + (size_t)idx];
        float wm = g_w[m];
        acc.x = fmaf(wm, v.x, acc.x);
        acc.y = fmaf(wm, v.y, acc.y);
        acc.z = fmaf(wm, v.z, acc.z);
        acc.w = fmaf(wm, v.w, acc.w);
    }
    out[i] = acc;
}

// ---------------------------------------------------------------------------
// Launch contract
// Inputs (metadata order): task_emb [1,1024] f32, K_memory [16,1024] f32,
//                          V0 [16,1024,1024] f32, V1 [16,1024,4096] f32
// Output: rec0 [1024,1024] f32 followed by rec1 [1024,4096] f32
// ---------------------------------------------------------------------------
extern "C" void kernel_launch(void* const* d_in, const int* in_sizes, int n_in,
                              void* d_out, int out_size) {
    const float* task_emb = (const float*)d_in[0];
    const float* K_memory = (const float*)d_in[1];
    const float* V0       = (const float*)d_in[2];
    const float* V1       = (const float*)d_in[3];
    float* out = (float*)d_out;

    const int n0 = in_sizes[2] / M_SLOTS;   // 1024*1024
    const int n1 = in_sizes[3] / M_SLOTS;   // 1024*4096
    const int nv4_0 = n0 / 4;               // 262144
    const int nv4_1 = n1 / 4;               // 1048576
    const int total = nv4_0 + nv4_1;        // 1310720 = 5120 * 256 exactly

    weights_kernel<<<M_SLOTS, TPB>>>(task_emb, K_memory);

    // Secondary with programmatic stream serialization (slightly positive).
    cudaLaunchConfig_t cfg = {};
    cfg.gridDim  = dim3((unsigned)(total / TPB));
    cfg.blockDim = dim3(TPB);
    cfg.dynamicSmemBytes = 0;
    cfg.stream = 0;

    cudaLaunchAttribute attrs[1];
    attrs[0].id = cudaLaunchAttributeProgrammaticStreamSerialization;
    attrs[0].val.programmaticStreamSerializationAllowed = 1;
    cfg.attrs = attrs;
    cfg.numAttrs = 1;

    cudaLaunchKernelEx(&cfg, wsum_fused_kernel,
                       (const float4*)V0, (const float4*)V1,
                       (float4*)out, nv4_0, nv4_1);
}